// round 3
// baseline (speedup 1.0000x reference)
#include <cuda_runtime.h>
#include <cuda_bf16.h>
#include <stdint.h>

#define DI __device__ __forceinline__

constexpr float SIG_SCALE = 0.125f;             // 1/sqrt(64)
constexpr float SIG_BIAS  = -7.6246189861594f;  // -log(2048)

// ---------------- scratch (static device globals; no allocation) ----------------
#define SCR_ELEMS (4u * 8u * 2048u * 64u)  // 4,194,304
__device__ __align__(16) __nv_bfloat16 g_qhi[SCR_ELEMS];
__device__ __align__(16) __nv_bfloat16 g_qlo[SCR_ELEMS];
__device__ __align__(16) __nv_bfloat16 g_khi[SCR_ELEMS];
__device__ __align__(16) __nv_bfloat16 g_klo[SCR_ELEMS];
__device__ __align__(16) __nv_bfloat16 g_vhi[SCR_ELEMS];  // V^T: [B,H,D,S]
__device__ __align__(16) __nv_bfloat16 g_vlo[SCR_ELEMS];
__device__ __align__(16) __nv_bfloat16 g_ohi[SCR_ELEMS];  // AO: [8192, 512]
__device__ __align__(16) __nv_bfloat16 g_olo[SCR_ELEMS];

// ---------------- helpers ----------------
DI uint32_t smem_u32(const void* p) {
    uint32_t a;
    asm("{ .reg .u64 t; cvta.to.shared.u64 t, %1; cvt.u32.u64 %0, t; }" : "=r"(a) : "l"(p));
    return a;
}

DI void ldsm4(uint32_t* r, uint32_t a) {
    asm volatile("ldmatrix.sync.aligned.m8n8.x4.shared.b16 {%0,%1,%2,%3}, [%4];"
                 : "=r"(r[0]), "=r"(r[1]), "=r"(r[2]), "=r"(r[3]) : "r"(a));
}

// D += A * B  (m16n8k16, bf16 in, fp32 acc)
DI void mma_bf(float* c, const uint32_t* a, const uint32_t* b) {
    asm volatile(
        "mma.sync.aligned.m16n8k16.row.col.f32.bf16.bf16.f32 "
        "{%0,%1,%2,%3}, {%4,%5,%6,%7}, {%8,%9}, {%0,%1,%2,%3};"
        : "+f"(c[0]), "+f"(c[1]), "+f"(c[2]), "+f"(c[3])
        : "r"(a[0]), "r"(a[1]), "r"(a[2]), "r"(a[3]), "r"(b[0]), "r"(b[1]));
}

DI void split_s(float f, __nv_bfloat16& h, __nv_bfloat16& l) {
    h = __float2bfloat16_rn(f);
    l = __float2bfloat16_rn(f - __bfloat162float(h));
}

// split two floats into packed-bf16x2 hi and lo words
DI void splitpack(float f0, float f1, uint32_t& ph, uint32_t& pl) {
    __nv_bfloat162 vh, vl;
    vh.x = __float2bfloat16_rn(f0);
    vh.y = __float2bfloat16_rn(f1);
    float r0 = f0 - __bfloat162float(vh.x);
    float r1 = f1 - __bfloat162float(vh.y);
    vl.x = __float2bfloat16_rn(r0);
    vl.y = __float2bfloat16_rn(r1);
    ph = *reinterpret_cast<uint32_t*>(&vh);
    pl = *reinterpret_cast<uint32_t*>(&vl);
}

// =====================================================================
// Kernel 1: QKV projection. C[8192,512] = x @ W^T  (z selects W).
// BM=128 BN=128 BK=32, 256 thr (8 warps as 4m x 2n), split-bf16 3-combo.
// =====================================================================
constexpr int AST = 40;  // smem row stride (elems): 80B, 16B-mult, LDSM conflict-free

__global__ __launch_bounds__(256, 1) void k_qkv(const float* __restrict__ x,
                                                const float* __restrict__ Wq,
                                                const float* __restrict__ Wk,
                                                const float* __restrict__ Wv) {
    __shared__ __nv_bfloat16 sAh[128 * AST], sAl[128 * AST];
    __shared__ __nv_bfloat16 sBh[128 * AST], sBl[128 * AST];
    const int tid = threadIdx.x, lid = tid & 31, w = tid >> 5;
    const int wm = w >> 1, wn = w & 1;
    const int m0 = blockIdx.x * 128, n0 = blockIdx.y * 128, z = blockIdx.z;
    const float* __restrict__ W = (z == 0) ? Wq : ((z == 1) ? Wk : Wv);
    const uint32_t uAh = smem_u32(sAh), uAl = smem_u32(sAl);
    const uint32_t uBh = smem_u32(sBh), uBl = smem_u32(sBl);
    const int g = lid >> 2, t = lid & 3;

    float acc[2][8][4];
#pragma unroll
    for (int mf = 0; mf < 2; mf++)
#pragma unroll
        for (int nf = 0; nf < 8; nf++)
#pragma unroll
            for (int e = 0; e < 4; e++) acc[mf][nf][e] = 0.0f;

    for (int c = 0; c < 16; c++) {
        __syncthreads();
#pragma unroll
        for (int it = 0; it < 4; it++) {
            int i = tid + it * 256, r = i >> 3, q = i & 7;
            float4 f = ((const float4*)x)[(size_t)(m0 + r) * 128 + c * 8 + q];
            uint32_t h0, l0, h1, l1;
            splitpack(f.x, f.y, h0, l0);
            splitpack(f.z, f.w, h1, l1);
            *(uint2*)(sAh + r * AST + q * 4) = make_uint2(h0, h1);
            *(uint2*)(sAl + r * AST + q * 4) = make_uint2(l0, l1);
        }
#pragma unroll
        for (int it = 0; it < 4; it++) {
            int i = tid + it * 256, r = i >> 3, q = i & 7;
            float4 f = ((const float4*)W)[(size_t)(n0 + r) * 128 + c * 8 + q];
            uint32_t h0, l0, h1, l1;
            splitpack(f.x, f.y, h0, l0);
            splitpack(f.z, f.w, h1, l1);
            *(uint2*)(sBh + r * AST + q * 4) = make_uint2(h0, h1);
            *(uint2*)(sBl + r * AST + q * 4) = make_uint2(l0, l1);
        }
        __syncthreads();

        uint32_t ah[2][2][4], al[2][2][4];
#pragma unroll
        for (int mf = 0; mf < 2; mf++)
#pragma unroll
            for (int kk = 0; kk < 2; kk++) {
                uint32_t off =
                    (uint32_t)(((wm * 32 + mf * 16 + (lid & 15)) * AST + kk * 16 + (lid >> 4) * 8) * 2);
                ldsm4(ah[mf][kk], uAh + off);
                ldsm4(al[mf][kk], uAl + off);
            }
#pragma unroll
        for (int nf = 0; nf < 8; nf++) {
            uint32_t bh[4], bl[4];
            uint32_t off = (uint32_t)(((wn * 64 + nf * 8 + (lid & 7)) * AST + (lid >> 3) * 8) * 2);
            ldsm4(bh, uBh + off);
            ldsm4(bl, uBl + off);
#pragma unroll
            for (int mf = 0; mf < 2; mf++)
#pragma unroll
                for (int kk = 0; kk < 2; kk++) {
                    mma_bf(acc[mf][nf], ah[mf][kk], bh + kk * 2);
                    mma_bf(acc[mf][nf], ah[mf][kk], bl + kk * 2);
                    mma_bf(acc[mf][nf], al[mf][kk], bh + kk * 2);
                }
        }
    }

    // epilogue: split to scratch
#pragma unroll
    for (int mf = 0; mf < 2; mf++) {
        int m = m0 + wm * 32 + mf * 16 + g;
        int b = m >> 11, s = m & 2047;
#pragma unroll
        for (int nf = 0; nf < 8; nf++) {
            int n = n0 + wn * 64 + nf * 8 + 2 * t;
            int h = n >> 6, d = n & 63;
            float* cc = acc[mf][nf];
            if (z < 2) {
                __nv_bfloat16* dh = (z == 0) ? g_qhi : g_khi;
                __nv_bfloat16* dl = (z == 0) ? g_qlo : g_klo;
                uint32_t h01, l01, h23, l23;
                splitpack(cc[0], cc[1], h01, l01);
                splitpack(cc[2], cc[3], h23, l23);
                size_t o0 = ((size_t)(b * 8 + h) * 2048 + s) * 64 + d;
                *(uint32_t*)(dh + o0) = h01;
                *(uint32_t*)(dl + o0) = l01;
                size_t o1 = o0 + 8 * 64;  // row s+8
                *(uint32_t*)(dh + o1) = h23;
                *(uint32_t*)(dl + o1) = l23;
            } else {
                // V^T [bh][d][s]: c0->(d,s) c1->(d+1,s) c2->(d,s+8) c3->(d+1,s+8)
                __nv_bfloat16 h0, l0, h1, l1, h2, l2, h3, l3;
                split_s(cc[0], h0, l0);
                split_s(cc[1], h1, l1);
                split_s(cc[2], h2, l2);
                split_s(cc[3], h3, l3);
                size_t o0 = ((size_t)(b * 8 + h) * 64 + d) * 2048 + s;
                g_vhi[o0] = h0;           g_vlo[o0] = l0;
                g_vhi[o0 + 2048] = h1;    g_vlo[o0 + 2048] = l1;
                g_vhi[o0 + 8] = h2;       g_vlo[o0 + 8] = l2;
                g_vhi[o0 + 2056] = h3;    g_vlo[o0 + 2056] = l3;
            }
        }
    }
}

// =====================================================================
// Kernel 2: fused sigmoid attention. Per (q-tile 128, bh):
// 8 warps x 16 q-rows; S (16x128) in regs, sigmoid, P@V accumulated.
// =====================================================================
constexpr int KST = 72;    // K-tile smem stride (144B)
constexpr int VST = 136;   // V-tile smem stride (272B)
constexpr int ATTN_SMEM = (128 * KST * 2 + 64 * VST * 2) * 2;  // 71680 B

__global__ __launch_bounds__(256, 1) void k_attn() {
    extern __shared__ __nv_bfloat16 dsm[];
    __nv_bfloat16* sKh = dsm;
    __nv_bfloat16* sKl = dsm + 128 * KST;
    __nv_bfloat16* sVh = dsm + 2 * 128 * KST;
    __nv_bfloat16* sVl = dsm + 2 * 128 * KST + 64 * VST;
    const uint32_t uKh = smem_u32(sKh), uKl = smem_u32(sKl);
    const uint32_t uVh = smem_u32(sVh), uVl = smem_u32(sVl);

    const int tid = threadIdx.x, lid = tid & 31, w = tid >> 5;
    const int q0 = blockIdx.x * 128, bh = blockIdx.y;
    const int g = lid >> 2, t = lid & 3;

    // Q fragments for this warp's 16 rows (resident whole kernel)
    uint32_t qh[4][4], ql[4][4];
    {
        const __nv_bfloat16* Qh = g_qhi + ((size_t)bh * 2048 + q0 + w * 16) * 64;
        const __nv_bfloat16* Ql = g_qlo + ((size_t)bh * 2048 + q0 + w * 16) * 64;
#pragma unroll
        for (int kk = 0; kk < 4; kk++) {
            int c0 = kk * 16 + 2 * t;
            qh[kk][0] = *(const uint32_t*)(Qh + g * 64 + c0);
            qh[kk][1] = *(const uint32_t*)(Qh + (g + 8) * 64 + c0);
            qh[kk][2] = *(const uint32_t*)(Qh + g * 64 + c0 + 8);
            qh[kk][3] = *(const uint32_t*)(Qh + (g + 8) * 64 + c0 + 8);
            ql[kk][0] = *(const uint32_t*)(Ql + g * 64 + c0);
            ql[kk][1] = *(const uint32_t*)(Ql + (g + 8) * 64 + c0);
            ql[kk][2] = *(const uint32_t*)(Ql + g * 64 + c0 + 8);
            ql[kk][3] = *(const uint32_t*)(Ql + (g + 8) * 64 + c0 + 8);
        }
    }

    float oacc[8][4];
#pragma unroll
    for (int nf = 0; nf < 8; nf++)
#pragma unroll
        for (int e = 0; e < 4; e++) oacc[nf][e] = 0.0f;

    for (int j = 0; j < 16; j++) {
        __syncthreads();
        {
            const float4* Kh = (const float4*)(g_khi + ((size_t)bh * 2048 + j * 128) * 64);
            const float4* Kl = (const float4*)(g_klo + ((size_t)bh * 2048 + j * 128) * 64);
#pragma unroll
            for (int it = 0; it < 4; it++) {
                int i = tid + it * 256, r = i >> 3, q = i & 7;
                *(float4*)(sKh + r * KST + q * 8) = Kh[r * 8 + q];
                *(float4*)(sKl + r * KST + q * 8) = Kl[r * 8 + q];
            }
            const float4* Vh = (const float4*)(g_vhi + (size_t)bh * 131072 + j * 128);
            const float4* Vl = (const float4*)(g_vlo + (size_t)bh * 131072 + j * 128);
#pragma unroll
            for (int it = 0; it < 4; it++) {
                int i = tid + it * 256, r = i >> 4, q = i & 15;
                *(float4*)(sVh + r * VST + q * 8) = Vh[r * 256 + q];
                *(float4*)(sVl + r * VST + q * 8) = Vl[r * 256 + q];
            }
        }
        __syncthreads();

        // S = Q @ K^T for this kv tile (16 x 128)
        float sacc[16][4];
#pragma unroll
        for (int nf = 0; nf < 16; nf++)
#pragma unroll
            for (int e = 0; e < 4; e++) sacc[nf][e] = 0.0f;

#pragma unroll
        for (int nf = 0; nf < 16; nf++) {
            uint32_t kh[8], kl[8];
            uint32_t base = (uint32_t)((nf * 8 + (lid & 7)) * KST + (lid >> 3) * 8);
            ldsm4(kh, uKh + base * 2);
            ldsm4(kh + 4, uKh + (base + 32) * 2);
            ldsm4(kl, uKl + base * 2);
            ldsm4(kl + 4, uKl + (base + 32) * 2);
#pragma unroll
            for (int kk = 0; kk < 4; kk++) {
                mma_bf(sacc[nf], qh[kk], kh + 2 * kk);
                mma_bf(sacc[nf], qh[kk], kl + 2 * kk);
                mma_bf(sacc[nf], ql[kk], kh + 2 * kk);
            }
        }

        // sigmoid
#pragma unroll
        for (int nf = 0; nf < 16; nf++)
#pragma unroll
            for (int e = 0; e < 4; e++) {
                float v = sacc[nf][e] * SIG_SCALE + SIG_BIAS;
                sacc[nf][e] = __fdividef(1.0f, 1.0f + __expf(-v));
            }

        // O += P @ V (k = 128 over s, in 4 chunks of 32)
#pragma unroll
        for (int kc = 0; kc < 4; kc++) {
            uint32_t ph[2][4], pl[2][4];
#pragma unroll
            for (int u = 0; u < 2; u++) {
                float* s0 = sacc[(2 * kc + u) * 2];
                float* s1 = sacc[(2 * kc + u) * 2 + 1];
                splitpack(s0[0], s0[1], ph[u][0], pl[u][0]);
                splitpack(s0[2], s0[3], ph[u][1], pl[u][1]);
                splitpack(s1[0], s1[1], ph[u][2], pl[u][2]);
                splitpack(s1[2], s1[3], ph[u][3], pl[u][3]);
            }
#pragma unroll
            for (int nf = 0; nf < 8; nf++) {
                uint32_t vh[4], vl[4];
                uint32_t off =
                    (uint32_t)(((nf * 8 + (lid & 7)) * VST + kc * 32 + (lid >> 3) * 8) * 2);
                ldsm4(vh, uVh + off);
                ldsm4(vl, uVl + off);
#pragma unroll
                for (int u = 0; u < 2; u++) {
                    mma_bf(oacc[nf], ph[u], vh + 2 * u);
                    mma_bf(oacc[nf], ph[u], vl + 2 * u);
                    mma_bf(oacc[nf], pl[u], vh + 2 * u);
                }
            }
        }
    }

    // epilogue: split O -> AO scratch [8192, 512]
    {
        const int b = bh >> 3, h = bh & 7;
        const int s = q0 + w * 16 + g;
#pragma unroll
        for (int nf = 0; nf < 8; nf++) {
            int d = nf * 8 + 2 * t;
            uint32_t h01, l01, h23, l23;
            splitpack(oacc[nf][0], oacc[nf][1], h01, l01);
            splitpack(oacc[nf][2], oacc[nf][3], h23, l23);
            size_t o0 = ((size_t)b * 2048 + s) * 512 + h * 64 + d;
            *(uint32_t*)(g_ohi + o0) = h01;
            *(uint32_t*)(g_olo + o0) = l01;
            size_t o1 = o0 + 8 * 512;
            *(uint32_t*)(g_ohi + o1) = h23;
            *(uint32_t*)(g_olo + o1) = l23;
        }
    }
}

// =====================================================================
// Kernel 3: output projection. out[8192,512] = AO @ Wo^T (fp32 out)
// =====================================================================
__global__ __launch_bounds__(256, 1) void k_out(const float* __restrict__ Wo,
                                                float* __restrict__ out) {
    __shared__ __nv_bfloat16 sAh[128 * AST], sAl[128 * AST];
    __shared__ __nv_bfloat16 sBh[128 * AST], sBl[128 * AST];
    const int tid = threadIdx.x, lid = tid & 31, w = tid >> 5;
    const int wm = w >> 1, wn = w & 1;
    const int m0 = blockIdx.x * 128, n0 = blockIdx.y * 128;
    const uint32_t uAh = smem_u32(sAh), uAl = smem_u32(sAl);
    const uint32_t uBh = smem_u32(sBh), uBl = smem_u32(sBl);
    const int g = lid >> 2, t = lid & 3;

    float acc[2][8][4];
#pragma unroll
    for (int mf = 0; mf < 2; mf++)
#pragma unroll
        for (int nf = 0; nf < 8; nf++)
#pragma unroll
            for (int e = 0; e < 4; e++) acc[mf][nf][e] = 0.0f;

    for (int c = 0; c < 16; c++) {
        __syncthreads();
#pragma unroll
        for (int it = 0; it < 2; it++) {
            int i = tid + it * 256, r = i >> 2, q = i & 3;
            size_t src = (size_t)(m0 + r) * 64 + c * 4 + q;
            *(float4*)(sAh + r * AST + q * 8) = ((const float4*)g_ohi)[src];
            *(float4*)(sAl + r * AST + q * 8) = ((const float4*)g_olo)[src];
        }
#pragma unroll
        for (int it = 0; it < 4; it++) {
            int i = tid + it * 256, r = i >> 3, q = i & 7;
            float4 f = ((const float4*)Wo)[(size_t)(n0 + r) * 128 + c * 8 + q];
            uint32_t h0, l0, h1, l1;
            splitpack(f.x, f.y, h0, l0);
            splitpack(f.z, f.w, h1, l1);
            *(uint2*)(sBh + r * AST + q * 4) = make_uint2(h0, h1);
            *(uint2*)(sBl + r * AST + q * 4) = make_uint2(l0, l1);
        }
        __syncthreads();

        uint32_t ah[2][2][4], al[2][2][4];
#pragma unroll
        for (int mf = 0; mf < 2; mf++)
#pragma unroll
            for (int kk = 0; kk < 2; kk++) {
                uint32_t off =
                    (uint32_t)(((wm * 32 + mf * 16 + (lid & 15)) * AST + kk * 16 + (lid >> 4) * 8) * 2);
                ldsm4(ah[mf][kk], uAh + off);
                ldsm4(al[mf][kk], uAl + off);
            }
#pragma unroll
        for (int nf = 0; nf < 8; nf++) {
            uint32_t bh[4], bl[4];
            uint32_t off = (uint32_t)(((wn * 64 + nf * 8 + (lid & 7)) * AST + (lid >> 3) * 8) * 2);
            ldsm4(bh, uBh + off);
            ldsm4(bl, uBl + off);
#pragma unroll
            for (int mf = 0; mf < 2; mf++)
#pragma unroll
                for (int kk = 0; kk < 2; kk++) {
                    mma_bf(acc[mf][nf], ah[mf][kk], bh + kk * 2);
                    mma_bf(acc[mf][nf], ah[mf][kk], bl + kk * 2);
                    mma_bf(acc[mf][nf], al[mf][kk], bh + kk * 2);
                }
        }
    }

    // epilogue: fp32 direct to output
#pragma unroll
    for (int mf = 0; mf < 2; mf++) {
        int m = m0 + wm * 32 + mf * 16 + g;
#pragma unroll
        for (int nf = 0; nf < 8; nf++) {
            int n = n0 + wn * 64 + nf * 8 + 2 * t;
            float* cc = acc[mf][nf];
            *(float2*)(out + (size_t)m * 512 + n) = make_float2(cc[0], cc[1]);
            *(float2*)(out + (size_t)(m + 8) * 512 + n) = make_float2(cc[2], cc[3]);
        }
    }
}

// =====================================================================
extern "C" void kernel_launch(void* const* d_in, const int* in_sizes, int n_in,
                              void* d_out, int out_size) {
    const float* x = (const float*)d_in[0];
    const float* Wq = (const float*)d_in[1];
    const float* Wk = (const float*)d_in[2];
    const float* Wv = (const float*)d_in[3];
    const float* Wo = (const float*)d_in[4];
    float* out = (float*)d_out;

    cudaFuncSetAttribute(k_attn, cudaFuncAttributeMaxDynamicSharedMemorySize, ATTN_SMEM);

    k_qkv<<<dim3(64, 4, 3), 256>>>(x, Wq, Wk, Wv);
    k_attn<<<dim3(16, 32), 256, ATTN_SMEM>>>();
    k_out<<<dim3(64, 4), 256>>>(Wo, out);
}